// round 1
// baseline (speedup 1.0000x reference)
#include <cuda_runtime.h>

// Problem constants
#define NB      16
#define CDIM    64
#define HWDIM   4096          // 64*64
#define NTOT    65536         // NB*HWDIM
#define KCB     512           // n_embeddings
#define OUT_Q   4194304       // NB*CDIM*HWDIM
// out layout (all f32): [quantized OUT_Q][loss][perplexity][active][indices NTOT]
#define OFF_LOSS (OUT_Q)
#define OFF_PERP (OUT_Q + 1)
#define OFF_ACT  (OUT_Q + 2)
#define OFF_IDX  (OUT_Q + 3)

#define SMEM_BYTES (KCB*CDIM*4 + KCB*4 + KCB*4)   // E + hist + norms = 135168

__device__ float        g_enorm[KCB];
__device__ float        g_loss;
__device__ unsigned int g_hist[KCB];

// ---------------------------------------------------------------------------
// init: codebook row norms + zero accumulators (runs every launch -> graph-safe)
// ---------------------------------------------------------------------------
__global__ void vq_init(const float* __restrict__ E) {
    int k = threadIdx.x;                        // 512 threads
    const float4* row = reinterpret_cast<const float4*>(E + k * CDIM);
    float s = 0.f;
#pragma unroll
    for (int i = 0; i < CDIM / 4; i++) {
        float4 v = row[i];
        s = fmaf(v.x, v.x, s);
        s = fmaf(v.y, v.y, s);
        s = fmaf(v.z, v.z, s);
        s = fmaf(v.w, v.w, s);
    }
    g_enorm[k] = s;
    g_hist[k]  = 0u;
    if (k == 0) g_loss = 0.f;
}

// ---------------------------------------------------------------------------
// main: per-point argmin over 512 codes, write quantized output + index,
//       shared histogram + block loss reduction
// ---------------------------------------------------------------------------
extern __shared__ float s_dyn[];

__global__ __launch_bounds__(512, 1)
void vq_main(const float* __restrict__ x,
             const float* __restrict__ E,
             float* __restrict__ out) {
    float*        sE    = s_dyn;                                // KCB*CDIM
    unsigned int* shist = (unsigned int*)(s_dyn + KCB * CDIM);  // KCB
    float*        snorm = (float*)(shist + KCB);                // KCB
    __shared__ float s_warpsum[16];

    const int tid = threadIdx.x;

    // stage codebook into smem (coalesced float4)
    {
        const float4* Eg  = reinterpret_cast<const float4*>(E);
        float4*       sE4 = reinterpret_cast<float4*>(sE);
#pragma unroll
        for (int i = tid; i < KCB * CDIM / 4; i += 512) sE4[i] = Eg[i];
    }
    if (tid < KCB) { snorm[tid] = g_enorm[tid]; shist[tid] = 0u; }
    __syncthreads();

    const int n  = blockIdx.x * 512 + tid;      // one point per thread, grid==NTOT
    const int b  = n >> 12;
    const int hw = n & (HWDIM - 1);

    // load x row (BCHW: stride HWDIM along channels; coalesced across threads)
    const float* xp = x + (size_t)b * CDIM * HWDIM + hw;
    float xr[CDIM];
    float xnorm = 0.f;
#pragma unroll
    for (int c = 0; c < CDIM; c++) {
        xr[c]  = xp[(size_t)c * HWDIM];
        xnorm  = fmaf(xr[c], xr[c], xnorm);
    }

    // argmin_k  ||e_k||^2 - 2 x.e_k   (||x||^2 constant per row)
    float bestd = 3.4e38f;
    int   bestk = 0;
#pragma unroll 1
    for (int k = 0; k < KCB; k++) {
        const float4* e4 = reinterpret_cast<const float4*>(sE + k * CDIM);
        float a0 = 0.f, a1 = 0.f, a2 = 0.f, a3 = 0.f;
#pragma unroll
        for (int i = 0; i < CDIM / 4; i++) {
            float4 ev = e4[i];                  // broadcast LDS.128
            a0 = fmaf(xr[4*i+0], ev.x, a0);
            a1 = fmaf(xr[4*i+1], ev.y, a1);
            a2 = fmaf(xr[4*i+2], ev.z, a2);
            a3 = fmaf(xr[4*i+3], ev.w, a3);
        }
        float dot  = (a0 + a1) + (a2 + a3);
        float dist = fmaf(-2.f, dot, snorm[k]);
        if (dist < bestd) { bestd = dist; bestk = k; }   // strict < keeps first
    }

    // commitment-loss contribution: ||x - e_best||^2 = bestd + ||x||^2
    float lossn = bestd + xnorm;

    atomicAdd(&shist[bestk], 1u);

    // write quantized output (gather code row from gmem/L2; strided coalesced store)
    {
        const float4* eg = reinterpret_cast<const float4*>(E + bestk * CDIM);
        float*        op = out + (size_t)b * CDIM * HWDIM + hw;
#pragma unroll
        for (int i = 0; i < CDIM / 4; i++) {
            float4 ev = eg[i];
            op[(size_t)(4*i+0) * HWDIM] = ev.x;
            op[(size_t)(4*i+1) * HWDIM] = ev.y;
            op[(size_t)(4*i+2) * HWDIM] = ev.z;
            op[(size_t)(4*i+3) * HWDIM] = ev.w;
        }
    }
    out[OFF_IDX + n] = (float)bestk;

    // block-reduce loss
#pragma unroll
    for (int off = 16; off; off >>= 1)
        lossn += __shfl_xor_sync(0xFFFFFFFFu, lossn, off);
    if ((tid & 31) == 0) s_warpsum[tid >> 5] = lossn;
    __syncthreads();

    if (tid < KCB) atomicAdd(&g_hist[tid], shist[tid]);
    if (tid == 0) {
        float bsum = 0.f;
#pragma unroll
        for (int i = 0; i < 16; i++) bsum += s_warpsum[i];
        atomicAdd(&g_loss, bsum);
    }
}

// ---------------------------------------------------------------------------
// finalize: perplexity + loss + active_codes scalars
// ---------------------------------------------------------------------------
__global__ void vq_finalize(const float* __restrict__ w, float* __restrict__ out) {
    __shared__ float s_ent[16];
    __shared__ float s_act[16];
    int t = threadIdx.x;                        // 512 threads, one code each

    float p   = (float)g_hist[t] * (1.0f / (float)NTOT);
    float ent = p * logf(p + 1e-10f);
    float act = (w[t] >= 0.01f) ? 1.f : 0.f;

#pragma unroll
    for (int off = 16; off; off >>= 1) {
        ent += __shfl_xor_sync(0xFFFFFFFFu, ent, off);
        act += __shfl_xor_sync(0xFFFFFFFFu, act, off);
    }
    if ((t & 31) == 0) { s_ent[t >> 5] = ent; s_act[t >> 5] = act; }
    __syncthreads();
    if (t == 0) {
        float esum = 0.f, asum = 0.f;
#pragma unroll
        for (int i = 0; i < 16; i++) { esum += s_ent[i]; asum += s_act[i]; }
        out[OFF_LOSS] = g_loss * (1.0f / ((float)NTOT * (float)CDIM));
        out[OFF_PERP] = expf(-esum);
        out[OFF_ACT]  = asum;
    }
}

// ---------------------------------------------------------------------------
extern "C" void kernel_launch(void* const* d_in, const int* in_sizes, int n_in,
                              void* d_out, int out_size) {
    const float* x = (const float*)d_in[0];   // [16,64,64,64]
    const float* E = (const float*)d_in[1];   // [512,64]
    const float* w = (const float*)d_in[2];   // [512]
    float* out = (float*)d_out;

    cudaFuncSetAttribute(vq_main, cudaFuncAttributeMaxDynamicSharedMemorySize,
                         SMEM_BYTES);

    vq_init<<<1, 512>>>(E);
    vq_main<<<NTOT / 512, 512, SMEM_BYTES>>>(x, E, out);
    vq_finalize<<<1, 512>>>(w, out);
}